// round 11
// baseline (speedup 1.0000x reference)
#include <cuda_runtime.h>
#include <cstdint>

// ContDecoder fused kernel, fp32 SIMT baseline.
//
// Shapes (from reference):
//   lr_fields    [8, 2, 64, 64]
//   context_grid [8, 32, 64, 64]
//   hr_eps       [8, 64, 64]
//   coord        [8, 16384, 2]
//   W0 [37,516]  b0[516]
//   W1 [553,256] b1[256]   (in = concat(act516, x_in37))
//   W2 [293,128] b2[128]
//   W3 [165,64]  b3[64]
//   W4 [101,32]  b4[32]
//   W5 [69,16]   b5[16]
//   W6 [16,2]    b6[2]
//   out [8, 16384, 2] float32

#define THREADS 256
#define TM 64

static constexpr int Bb   = 8;
static constexpr int Nn   = 16384;
static constexpr int CTXC = 32;
static constexpr int OUTC = 2;
static constexpr int INSZ = 37;

// smem layout (floats):
//   xin  : [37][64]   at 0
//   bufA : [516][64]  at 37*64
//   bufB : [256][64]  at 37*64 + 516*64
static constexpr int XIN_OFF  = 0;
static constexpr int BUFA_OFF = 37 * 64;
static constexpr int BUFB_OFF = BUFA_OFF + 516 * 64;
static constexpr int SMEM_FLOATS = BUFB_OFF + 256 * 64;   // 51776 floats
static constexpr int SMEM_BYTES  = SMEM_FLOATS * 4;       // 207104 bytes

__device__ __forceinline__ float relu_f(float x) { return x > 0.f ? x : 0.f; }

// Accumulate acc[jj*4+mm] += W[k][j0+jj] * A[k][tx*4+mm] over k in [0, KK).
// A is smem with row stride 64 floats; W is global row-major with row stride NF.
template <int KK, int NF>
__device__ __forceinline__ void accum_k(const float* __restrict__ W,
                                        const float* __restrict__ A,
                                        int j0, int tx, float acc[16]) {
    const float* __restrict__ Ap = A + tx * 4;
    const float* __restrict__ Wp = W + j0;
#pragma unroll 4
    for (int k = 0; k < KK; ++k) {
        float4 a = *reinterpret_cast<const float4*>(Ap + k * 64);
        float4 w = __ldg(reinterpret_cast<const float4*>(Wp + k * NF));
        acc[0]  += w.x * a.x; acc[1]  += w.x * a.y; acc[2]  += w.x * a.z; acc[3]  += w.x * a.w;
        acc[4]  += w.y * a.x; acc[5]  += w.y * a.y; acc[6]  += w.y * a.z; acc[7]  += w.y * a.w;
        acc[8]  += w.z * a.x; acc[9]  += w.z * a.y; acc[10] += w.z * a.z; acc[11] += w.z * a.w;
        acc[12] += w.w * a.x; acc[13] += w.w * a.y; acc[14] += w.w * a.z; acc[15] += w.w * a.w;
    }
}

// One MLP layer: actOut[NF][64] = relu(W^T @ [actIn (K1); xin (37 if CONCAT)] + b)
// W rows 0..K1-1 multiply actIn; rows K1..K1+36 multiply xin.
template <int K1, int NF, bool CONCAT>
__device__ __forceinline__ void mlp_layer(const float* __restrict__ W,
                                          const float* __restrict__ bias,
                                          const float* __restrict__ actIn,
                                          const float* __restrict__ xin,
                                          float* __restrict__ actOut,
                                          int tx, int ty) {
    constexpr int JT = (NF + 63) / 64;
#pragma unroll
    for (int jt = 0; jt < JT; ++jt) {
        const int j0 = jt * 64 + ty * 4;
        if (j0 < NF) {   // NF % 4 == 0 for all hidden layers -> all-or-nothing per thread
            float acc[16];
            float4 bv = __ldg(reinterpret_cast<const float4*>(bias + j0));
#pragma unroll
            for (int mm = 0; mm < 4; ++mm) {
                acc[0 + mm] = bv.x; acc[4 + mm] = bv.y;
                acc[8 + mm] = bv.z; acc[12 + mm] = bv.w;
            }
            accum_k<K1, NF>(W, actIn, j0, tx, acc);
            if (CONCAT) {
                accum_k<INSZ, NF>(W + (size_t)K1 * NF, xin, j0, tx, acc);
            }
#pragma unroll
            for (int jj = 0; jj < 4; ++jj) {
                float4 o;
                o.x = relu_f(acc[jj * 4 + 0]);
                o.y = relu_f(acc[jj * 4 + 1]);
                o.z = relu_f(acc[jj * 4 + 2]);
                o.w = relu_f(acc[jj * 4 + 3]);
                *reinterpret_cast<float4*>(actOut + (j0 + jj) * 64 + tx * 4) = o;
            }
        }
    }
}

__global__ void __launch_bounds__(THREADS, 1)
ContDecoder_15788299780267_kernel(
    const float* __restrict__ lr,     // [8,2,64,64]
    const float* __restrict__ ctx,    // [8,32,64,64]
    const float* __restrict__ eps,    // [8,64,64]
    const float* __restrict__ coord,  // [8,16384,2]
    const float* __restrict__ W0, const float* __restrict__ b0,
    const float* __restrict__ W1, const float* __restrict__ b1,
    const float* __restrict__ W2, const float* __restrict__ b2,
    const float* __restrict__ W3, const float* __restrict__ b3,
    const float* __restrict__ W4, const float* __restrict__ b4,
    const float* __restrict__ W5, const float* __restrict__ b5,
    const float* __restrict__ W6, const float* __restrict__ b6,
    float* __restrict__ out)          // [8,16384,2]
{
    extern __shared__ float smem[];
    float* xin  = smem + XIN_OFF;     // [37][64]
    float* bufA = smem + BUFA_OFF;    // [516][64]
    float* bufB = smem + BUFB_OFF;    // [256][64]

    const int tid = threadIdx.x;
    const int blk = blockIdx.x;
    const int b   = blk >> 8;              // 256 blocks per batch (16384/64)
    const int n0  = (blk & 255) * TM;

    // ---------------- Phase A: bilinear sampling -> x_in[37][64] ----------------
    // Reference samples swapaxes(img, 2, 3): value = img[b][c][x_idx][y_idx]
    // with x_idx driven by coord.x and y_idx by coord.y, zero padding.
    {
        const int m = tid & 63;         // point within tile
        const int g = tid >> 6;         // channel group 0..3
        const int p = n0 + m;
        const float cx = coord[((size_t)b * Nn + p) * 2 + 0];
        const float cy = coord[((size_t)b * Nn + p) * 2 + 1];
        const float gx = (cx + 1.0f) * 32.0f - 0.5f;   // over H dim (size 64)
        const float gy = (cy + 1.0f) * 32.0f - 0.5f;   // over W dim (size 64)
        const float fx0 = floorf(gx), fy0 = floorf(gy);
        const float wx = gx - fx0, wy = gy - fy0;
        const int ix0 = (int)fx0, iy0 = (int)fy0;
        const int ix1 = ix0 + 1,  iy1 = iy0 + 1;
        const bool vx0 = ((unsigned)ix0 < 64u), vx1 = ((unsigned)ix1 < 64u);
        const bool vy0 = ((unsigned)iy0 < 64u), vy1 = ((unsigned)iy1 < 64u);
        const float w00 = (vx0 && vy0) ? (1.f - wx) * (1.f - wy) : 0.f;
        const float w10 = (vx1 && vy0) ? wx * (1.f - wy) : 0.f;
        const float w01 = (vx0 && vy1) ? (1.f - wx) * wy : 0.f;
        const float w11 = (vx1 && vy1) ? wx * wy : 0.f;
        const int cx0 = min(max(ix0, 0), 63), cx1 = min(max(ix1, 0), 63);
        const int cy0 = min(max(iy0, 0), 63), cy1 = min(max(iy1, 0), 63);
        const int o00 = cx0 * 64 + cy0, o10 = cx1 * 64 + cy0;
        const int o01 = cx0 * 64 + cy1, o11 = cx1 * 64 + cy1;

        if (g == 0) {
            xin[32 * 64 + m] = cx;
            xin[33 * 64 + m] = cy;
        }
        for (int ci = g; ci < 35; ci += 4) {
            const float* src;
            int k;
            if (ci < 32)      { src = ctx + (size_t)(b * CTXC + ci) * 4096;        k = ci; }
            else if (ci < 34) { src = lr  + (size_t)(b * OUTC + (ci - 32)) * 4096; k = 34 + (ci - 32); }
            else              { src = eps + (size_t)b * 4096;                      k = 36; }
            float v = w00 * __ldg(src + o00) + w10 * __ldg(src + o10)
                    + w01 * __ldg(src + o01) + w11 * __ldg(src + o11);
            xin[k * 64 + m] = v;
        }
    }
    __syncthreads();

    // ---------------- Phase B: MLP ----------------
    const int tx = tid & 15;   // 4 points each  -> 64 points
    const int ty = tid >> 4;   // 4 cols each    -> 64 cols per tile

    mlp_layer<37, 516, false>(W0, b0, xin,  nullptr, bufA, tx, ty);
    __syncthreads();
    mlp_layer<516, 256, true>(W1, b1, bufA, xin, bufB, tx, ty);
    __syncthreads();
    mlp_layer<256, 128, true>(W2, b2, bufB, xin, bufA, tx, ty);
    __syncthreads();
    mlp_layer<128, 64, true>(W3, b3, bufA, xin, bufB, tx, ty);
    __syncthreads();
    mlp_layer<64, 32, true>(W4, b4, bufB, xin, bufA, tx, ty);
    __syncthreads();
    mlp_layer<32, 16, true>(W5, b5, bufA, xin, bufB, tx, ty);
    __syncthreads();

    // ---------------- Final layer: [16] -> [2], no relu ----------------
    if (tid < 64) {
        const int m = tid;
        float s0 = __ldg(b6 + 0), s1 = __ldg(b6 + 1);
#pragma unroll
        for (int k = 0; k < 16; ++k) {
            const float a = bufB[k * 64 + m];
            s0 += a * __ldg(W6 + k * 2 + 0);
            s1 += a * __ldg(W6 + k * 2 + 1);
        }
        float2 o; o.x = s0; o.y = s1;
        *reinterpret_cast<float2*>(out + ((size_t)b * Nn + n0 + m) * 2) = o;
    }
}

extern "C" void kernel_launch(void* const* d_in, const int* in_sizes, int n_in,
                              void* d_out, int out_size) {
    (void)in_sizes; (void)n_in; (void)out_size;
    const float* lr    = (const float*)d_in[0];
    const float* ctx   = (const float*)d_in[1];
    const float* eps   = (const float*)d_in[2];
    const float* coord = (const float*)d_in[3];
    const float* W0 = (const float*)d_in[4];  const float* b0 = (const float*)d_in[5];
    const float* W1 = (const float*)d_in[6];  const float* b1 = (const float*)d_in[7];
    const float* W2 = (const float*)d_in[8];  const float* b2 = (const float*)d_in[9];
    const float* W3 = (const float*)d_in[10]; const float* b3 = (const float*)d_in[11];
    const float* W4 = (const float*)d_in[12]; const float* b4 = (const float*)d_in[13];
    const float* W5 = (const float*)d_in[14]; const float* b5 = (const float*)d_in[15];
    const float* W6 = (const float*)d_in[16]; const float* b6 = (const float*)d_in[17];
    float* out = (float*)d_out;

    cudaFuncSetAttribute(ContDecoder_15788299780267_kernel,
                         cudaFuncAttributeMaxDynamicSharedMemorySize, SMEM_BYTES);

    const int grid = (Bb * Nn) / TM;   // 2048 CTAs
    ContDecoder_15788299780267_kernel<<<grid, THREADS, SMEM_BYTES>>>(
        lr, ctx, eps, coord,
        W0, b0, W1, b1, W2, b2, W3, b3, W4, b4, W5, b5, W6, b6,
        out);
}

// round 12
// speedup vs baseline: 1.8171x; 1.8171x over previous
#include <cuda_runtime.h>
#include <cstdint>

// ContDecoder fused kernel — fp32, packed f32x2 FFMA2 math, 512 threads/CTA.
//
// Shapes:
//   lr_fields    [8, 2, 64, 64]
//   context_grid [8, 32, 64, 64]
//   hr_eps       [8, 64, 64]
//   coord        [8, 16384, 2]
//   W0 [37,516]  b0[516]
//   W1 [553,256] b1[256]   (in = concat(act516, x_in37))
//   W2 [293,128] b2[128]
//   W3 [165,64]  b3[64]
//   W4 [101,32]  b4[32]
//   W5 [69,16]   b5[16]
//   W6 [16,2]    b6[2]
//   out [8, 16384, 2] float32

#define THREADS 512
#define TM 64

static constexpr int Bb   = 8;
static constexpr int Nn   = 16384;
static constexpr int CTXC = 32;
static constexpr int OUTC = 2;
static constexpr int INSZ = 37;

// smem layout (floats): xin[37][64], bufA[516][64], bufB[256][64]
static constexpr int XIN_OFF  = 0;
static constexpr int BUFA_OFF = 37 * 64;
static constexpr int BUFB_OFF = BUFA_OFF + 516 * 64;
static constexpr int SMEM_FLOATS = BUFB_OFF + 256 * 64;   // 51776 floats
static constexpr int SMEM_BYTES  = SMEM_FLOATS * 4;       // 207104 bytes

typedef unsigned long long ull;

// ---- packed fp32 pair helpers (sm_100+ f32x2 path -> SASS FFMA2) ----
__device__ __forceinline__ ull dup_f32x2(float x) {
    ull r;
    asm("mov.b64 %0, {%1, %1};" : "=l"(r) : "f"(x));
    return r;
}
__device__ __forceinline__ void ffma2(ull& d, ull a, ull b) {
    asm("fma.rn.f32x2 %0, %1, %2, %0;" : "+l"(d) : "l"(a), "l"(b));
}
__device__ __forceinline__ float2 unpack_f32x2(ull v) {
    float2 r;
    asm("mov.b64 {%0, %1}, %2;" : "=f"(r.x), "=f"(r.y) : "l"(v));
    return r;
}

// Accumulate: for 4 points (tx*4 + p) and NP col-pairs starting at j0:
//   acc[p][c] += (W[k][j0+2c], W[k][j0+2c+1]) * (A[k][pt], A[k][pt])
// A: smem, row stride 64. W: global row-major, row stride NF.
template <int KK, int NF, int CPT>
__device__ __forceinline__ void acc_k(const float* __restrict__ W,
                                      const float* __restrict__ A,
                                      int j0, int tx, ull acc[4][CPT / 2]) {
    constexpr int NP = CPT / 2;
    const float* __restrict__ Ap = A + tx * 4;
    const float* __restrict__ Wp = W + j0;
#pragma unroll 4
    for (int k = 0; k < KK; ++k) {
        float4 a = *reinterpret_cast<const float4*>(Ap + k * 64);
        ull ad0 = dup_f32x2(a.x);
        ull ad1 = dup_f32x2(a.y);
        ull ad2 = dup_f32x2(a.z);
        ull ad3 = dup_f32x2(a.w);

        ull wp[NP];
        const char* wrow = reinterpret_cast<const char*>(Wp) + (size_t)k * NF * 4;
        if constexpr (NP == 4) {
            ulonglong2 w01 = __ldg(reinterpret_cast<const ulonglong2*>(wrow));
            ulonglong2 w23 = __ldg(reinterpret_cast<const ulonglong2*>(wrow + 16));
            wp[0] = w01.x; wp[1] = w01.y; wp[2] = w23.x; wp[3] = w23.y;
        } else if constexpr (NP == 2) {
            ulonglong2 w01 = __ldg(reinterpret_cast<const ulonglong2*>(wrow));
            wp[0] = w01.x; wp[1] = w01.y;
        } else {
            wp[0] = __ldg(reinterpret_cast<const ull*>(wrow));
        }
#pragma unroll
        for (int c = 0; c < NP; ++c) {
            ffma2(acc[0][c], ad0, wp[c]);
            ffma2(acc[1][c], ad1, wp[c]);
            ffma2(acc[2][c], ad2, wp[c]);
            ffma2(acc[3][c], ad3, wp[c]);
        }
    }
}

// One col-pass of a layer: cols [jbase + ty*CPT, +CPT). Pairs over columns.
// W rows 0..K1-1 multiply actIn; rows K1..K1+36 multiply xin (if CONCAT).
template <int K1, int NF, int CPT, bool CONCAT>
__device__ __forceinline__ void layer_pass(const float* __restrict__ W,
                                           const float* __restrict__ bias,
                                           const float* __restrict__ actIn,
                                           const float* __restrict__ xin,
                                           float* __restrict__ actOut,
                                           int tx, int ty, int jbase) {
    constexpr int NP = CPT / 2;
    const int j0 = jbase + ty * CPT;
    if (j0 + CPT > NF) return;       // all-or-nothing per thread (NF even)

    ull acc[4][NP];
    {
        ull bp[NP];
#pragma unroll
        for (int c = 0; c < NP; ++c)
            bp[c] = __ldg(reinterpret_cast<const ull*>(bias + j0 + 2 * c));
#pragma unroll
        for (int p = 0; p < 4; ++p)
#pragma unroll
            for (int c = 0; c < NP; ++c)
                acc[p][c] = bp[c];
    }

    acc_k<K1, NF, CPT>(W, actIn, j0, tx, acc);
    if (CONCAT)
        acc_k<INSZ, NF, CPT>(W + (size_t)K1 * NF, xin, j0, tx, acc);

#pragma unroll
    for (int c = 0; c < NP; ++c) {
#pragma unroll
        for (int p = 0; p < 4; ++p) {
            float2 v = unpack_f32x2(acc[p][c]);
            v.x = fmaxf(v.x, 0.f);
            v.y = fmaxf(v.y, 0.f);
            const int m = tx * 4 + p;
            actOut[(j0 + 2 * c) * 64 + m]     = v.x;
            actOut[(j0 + 2 * c + 1) * 64 + m] = v.y;
        }
    }
}

__global__ void __launch_bounds__(THREADS, 1)
ContDecoder_15788299780267_kernel(
    const float* __restrict__ lr,     // [8,2,64,64]
    const float* __restrict__ ctx,    // [8,32,64,64]
    const float* __restrict__ eps,    // [8,64,64]
    const float* __restrict__ coord,  // [8,16384,2]
    const float* __restrict__ W0, const float* __restrict__ b0,
    const float* __restrict__ W1, const float* __restrict__ b1,
    const float* __restrict__ W2, const float* __restrict__ b2,
    const float* __restrict__ W3, const float* __restrict__ b3,
    const float* __restrict__ W4, const float* __restrict__ b4,
    const float* __restrict__ W5, const float* __restrict__ b5,
    const float* __restrict__ W6, const float* __restrict__ b6,
    float* __restrict__ out)          // [8,16384,2]
{
    extern __shared__ float smem[];
    float* xin  = smem + XIN_OFF;     // [37][64]
    float* bufA = smem + BUFA_OFF;    // [516][64]
    float* bufB = smem + BUFB_OFF;    // [256][64]

    const int tid = threadIdx.x;
    const int blk = blockIdx.x;
    const int b   = blk >> 8;              // 256 blocks per batch (16384/64)
    const int n0  = (blk & 255) * TM;

    // ---------------- Phase A: bilinear sampling -> x_in[37][64] ----------------
    // Reference samples swapaxes(img, 2, 3): value = img[b][c][x_idx][y_idx],
    // x_idx from coord.x, y_idx from coord.y, zero padding outside.
    {
        const int m = tid & 63;         // point within tile
        const int g = tid >> 6;         // channel group 0..7
        const int p = n0 + m;
        const float cx = coord[((size_t)b * Nn + p) * 2 + 0];
        const float cy = coord[((size_t)b * Nn + p) * 2 + 1];
        const float gx = (cx + 1.0f) * 32.0f - 0.5f;
        const float gy = (cy + 1.0f) * 32.0f - 0.5f;
        const float fx0 = floorf(gx), fy0 = floorf(gy);
        const float wx = gx - fx0, wy = gy - fy0;
        const int ix0 = (int)fx0, iy0 = (int)fy0;
        const int ix1 = ix0 + 1,  iy1 = iy0 + 1;
        const bool vx0 = ((unsigned)ix0 < 64u), vx1 = ((unsigned)ix1 < 64u);
        const bool vy0 = ((unsigned)iy0 < 64u), vy1 = ((unsigned)iy1 < 64u);
        const float w00 = (vx0 && vy0) ? (1.f - wx) * (1.f - wy) : 0.f;
        const float w10 = (vx1 && vy0) ? wx * (1.f - wy) : 0.f;
        const float w01 = (vx0 && vy1) ? (1.f - wx) * wy : 0.f;
        const float w11 = (vx1 && vy1) ? wx * wy : 0.f;
        const int cx0 = min(max(ix0, 0), 63), cx1 = min(max(ix1, 0), 63);
        const int cy0 = min(max(iy0, 0), 63), cy1 = min(max(iy1, 0), 63);
        const int o00 = cx0 * 64 + cy0, o10 = cx1 * 64 + cy0;
        const int o01 = cx0 * 64 + cy1, o11 = cx1 * 64 + cy1;

        if (g == 0) {
            xin[32 * 64 + m] = cx;
            xin[33 * 64 + m] = cy;
        }
        for (int ci = g; ci < 35; ci += 8) {
            const float* src;
            int k;
            if (ci < 32)      { src = ctx + (size_t)(b * CTXC + ci) * 4096;        k = ci; }
            else if (ci < 34) { src = lr  + (size_t)(b * OUTC + (ci - 32)) * 4096; k = 34 + (ci - 32); }
            else              { src = eps + (size_t)b * 4096;                      k = 36; }
            float v = w00 * __ldg(src + o00) + w10 * __ldg(src + o10)
                    + w01 * __ldg(src + o01) + w11 * __ldg(src + o11);
            xin[k * 64 + m] = v;
        }
    }
    __syncthreads();

    // ---------------- Phase B: MLP ----------------
    const int tx = tid & 15;   // 4 points each  -> 64 points
    const int ty = tid >> 4;   // 0..31, CPT cols each

    // L0: 37 -> 516  (passes: 256 + 256 + tail 4 cols)
    layer_pass<37, 516, 8, false>(W0, b0, xin, nullptr, bufA, tx, ty, 0);
    layer_pass<37, 516, 8, false>(W0, b0, xin, nullptr, bufA, tx, ty, 256);
    layer_pass<37, 516, 2, false>(W0, b0, xin, nullptr, bufA, tx, ty, 512);
    __syncthreads();
    // L1: 516+37 -> 256
    layer_pass<516, 256, 8, true>(W1, b1, bufA, xin, bufB, tx, ty, 0);
    __syncthreads();
    // L2: 256+37 -> 128
    layer_pass<256, 128, 4, true>(W2, b2, bufB, xin, bufA, tx, ty, 0);
    __syncthreads();
    // L3: 128+37 -> 64
    layer_pass<128, 64, 2, true>(W3, b3, bufA, xin, bufB, tx, ty, 0);
    __syncthreads();
    // L4: 64+37 -> 32   (ty < 16 active)
    layer_pass<64, 32, 2, true>(W4, b4, bufB, xin, bufA, tx, ty, 0);
    __syncthreads();
    // L5: 32+37 -> 16   (ty < 8 active)
    layer_pass<32, 16, 2, true>(W5, b5, bufA, xin, bufB, tx, ty, 0);
    __syncthreads();

    // ---------------- Final layer: [16] -> [2], no relu ----------------
    if (tid < 64) {
        const int m = tid;
        float s0 = __ldg(b6 + 0), s1 = __ldg(b6 + 1);
#pragma unroll
        for (int k = 0; k < 16; ++k) {
            const float a = bufB[k * 64 + m];
            s0 += a * __ldg(W6 + k * 2 + 0);
            s1 += a * __ldg(W6 + k * 2 + 1);
        }
        float2 o; o.x = s0; o.y = s1;
        *reinterpret_cast<float2*>(out + ((size_t)b * Nn + n0 + m) * 2) = o;
    }
}

extern "C" void kernel_launch(void* const* d_in, const int* in_sizes, int n_in,
                              void* d_out, int out_size) {
    (void)in_sizes; (void)n_in; (void)out_size;
    const float* lr    = (const float*)d_in[0];
    const float* ctx   = (const float*)d_in[1];
    const float* eps   = (const float*)d_in[2];
    const float* coord = (const float*)d_in[3];
    const float* W0 = (const float*)d_in[4];  const float* b0 = (const float*)d_in[5];
    const float* W1 = (const float*)d_in[6];  const float* b1 = (const float*)d_in[7];
    const float* W2 = (const float*)d_in[8];  const float* b2 = (const float*)d_in[9];
    const float* W3 = (const float*)d_in[10]; const float* b3 = (const float*)d_in[11];
    const float* W4 = (const float*)d_in[12]; const float* b4 = (const float*)d_in[13];
    const float* W5 = (const float*)d_in[14]; const float* b5 = (const float*)d_in[15];
    const float* W6 = (const float*)d_in[16]; const float* b6 = (const float*)d_in[17];
    float* out = (float*)d_out;

    cudaFuncSetAttribute(ContDecoder_15788299780267_kernel,
                         cudaFuncAttributeMaxDynamicSharedMemorySize, SMEM_BYTES);

    const int grid = (Bb * Nn) / TM;   // 2048 CTAs
    ContDecoder_15788299780267_kernel<<<grid, THREADS, SMEM_BYTES>>>(
        lr, ctx, eps, coord,
        W0, b0, W1, b1, W2, b2, W3, b3, W4, b4, W5, b5, W6, b6,
        out);
}

// round 13
// speedup vs baseline: 1.8193x; 1.0012x over previous
#include <cuda_runtime.h>
#include <cstdint>

// ContDecoder fused kernel — fp32, packed f32x2 FFMA2 math, 512 threads/CTA.
//
// Shapes:
//   lr_fields    [8, 2, 64, 64]
//   context_grid [8, 32, 64, 64]
//   hr_eps       [8, 64, 64]
//   coord        [8, 16384, 2]
//   W0 [37,516]  b0[516]
//   W1 [553,256] b1[256]   (in = concat(act516, x_in37))
//   W2 [293,128] b2[128]
//   W3 [165,64]  b3[64]
//   W4 [101,32]  b4[32]
//   W5 [69,16]   b5[16]
//   W6 [16,2]    b6[2]
//   out [8, 16384, 2] float32

#define THREADS 512
#define TM 64

static constexpr int Bb   = 8;
static constexpr int Nn   = 16384;
static constexpr int CTXC = 32;
static constexpr int OUTC = 2;
static constexpr int INSZ = 37;

// smem layout (floats): xin[37][64], bufA[516][64], bufB[256][64]
static constexpr int XIN_OFF  = 0;
static constexpr int BUFA_OFF = 37 * 64;
static constexpr int BUFB_OFF = BUFA_OFF + 516 * 64;
static constexpr int SMEM_FLOATS = BUFB_OFF + 256 * 64;   // 51776 floats
static constexpr int SMEM_BYTES  = SMEM_FLOATS * 4;       // 207104 bytes

typedef unsigned long long ull;

// ---- packed fp32 pair helpers (sm_100+ f32x2 path -> SASS FFMA2) ----
__device__ __forceinline__ ull dup_f32x2(float x) {
    ull r;
    asm("mov.b64 %0, {%1, %1};" : "=l"(r) : "f"(x));
    return r;
}
__device__ __forceinline__ void ffma2(ull& d, ull a, ull b) {
    asm("fma.rn.f32x2 %0, %1, %2, %0;" : "+l"(d) : "l"(a), "l"(b));
}
__device__ __forceinline__ float2 unpack_f32x2(ull v) {
    float2 r;
    asm("mov.b64 {%0, %1}, %2;" : "=f"(r.x), "=f"(r.y) : "l"(v));
    return r;
}

// Accumulate: for 4 points (tx*4 + p) and NP col-pairs starting at j0:
//   acc[p][c] += (W[k][j0+2c], W[k][j0+2c+1]) * (A[k][pt], A[k][pt])
// A: smem, row stride 64. W: global row-major, row stride NF.
template <int KK, int NF, int CPT>
__device__ __forceinline__ void acc_k(const float* __restrict__ W,
                                      const float* __restrict__ A,
                                      int j0, int tx, ull acc[4][CPT / 2]) {
    constexpr int NP = CPT / 2;
    const float* __restrict__ Ap = A + tx * 4;
    const float* __restrict__ Wp = W + j0;
#pragma unroll 4
    for (int k = 0; k < KK; ++k) {
        float4 a = *reinterpret_cast<const float4*>(Ap + k * 64);
        ull ad0 = dup_f32x2(a.x);
        ull ad1 = dup_f32x2(a.y);
        ull ad2 = dup_f32x2(a.z);
        ull ad3 = dup_f32x2(a.w);

        ull wp[NP];
        const char* wrow = reinterpret_cast<const char*>(Wp) + (size_t)k * NF * 4;
        if constexpr (NP == 4) {
            ulonglong2 w01 = __ldg(reinterpret_cast<const ulonglong2*>(wrow));
            ulonglong2 w23 = __ldg(reinterpret_cast<const ulonglong2*>(wrow + 16));
            wp[0] = w01.x; wp[1] = w01.y; wp[2] = w23.x; wp[3] = w23.y;
        } else if constexpr (NP == 2) {
            ulonglong2 w01 = __ldg(reinterpret_cast<const ulonglong2*>(wrow));
            wp[0] = w01.x; wp[1] = w01.y;
        } else {
            wp[0] = __ldg(reinterpret_cast<const ull*>(wrow));
        }
#pragma unroll
        for (int c = 0; c < NP; ++c) {
            ffma2(acc[0][c], ad0, wp[c]);
            ffma2(acc[1][c], ad1, wp[c]);
            ffma2(acc[2][c], ad2, wp[c]);
            ffma2(acc[3][c], ad3, wp[c]);
        }
    }
}

// One col-pass of a layer: cols [jbase + ty*CPT, +CPT). Pairs over columns.
// W rows 0..K1-1 multiply actIn; rows K1..K1+36 multiply xin (if CONCAT).
template <int K1, int NF, int CPT, bool CONCAT>
__device__ __forceinline__ void layer_pass(const float* __restrict__ W,
                                           const float* __restrict__ bias,
                                           const float* __restrict__ actIn,
                                           const float* __restrict__ xin,
                                           float* __restrict__ actOut,
                                           int tx, int ty, int jbase) {
    constexpr int NP = CPT / 2;
    const int j0 = jbase + ty * CPT;
    if (j0 + CPT > NF) return;       // all-or-nothing per thread (NF even)

    ull acc[4][NP];
    {
        ull bp[NP];
#pragma unroll
        for (int c = 0; c < NP; ++c)
            bp[c] = __ldg(reinterpret_cast<const ull*>(bias + j0 + 2 * c));
#pragma unroll
        for (int p = 0; p < 4; ++p)
#pragma unroll
            for (int c = 0; c < NP; ++c)
                acc[p][c] = bp[c];
    }

    acc_k<K1, NF, CPT>(W, actIn, j0, tx, acc);
    if (CONCAT)
        acc_k<INSZ, NF, CPT>(W + (size_t)K1 * NF, xin, j0, tx, acc);

#pragma unroll
    for (int c = 0; c < NP; ++c) {
#pragma unroll
        for (int p = 0; p < 4; ++p) {
            float2 v = unpack_f32x2(acc[p][c]);
            v.x = fmaxf(v.x, 0.f);
            v.y = fmaxf(v.y, 0.f);
            const int m = tx * 4 + p;
            actOut[(j0 + 2 * c) * 64 + m]     = v.x;
            actOut[(j0 + 2 * c + 1) * 64 + m] = v.y;
        }
    }
}

__global__ void __launch_bounds__(THREADS, 1)
ContDecoder_15788299780267_kernel(
    const float* __restrict__ lr,     // [8,2,64,64]
    const float* __restrict__ ctx,    // [8,32,64,64]
    const float* __restrict__ eps,    // [8,64,64]
    const float* __restrict__ coord,  // [8,16384,2]
    const float* __restrict__ W0, const float* __restrict__ b0,
    const float* __restrict__ W1, const float* __restrict__ b1,
    const float* __restrict__ W2, const float* __restrict__ b2,
    const float* __restrict__ W3, const float* __restrict__ b3,
    const float* __restrict__ W4, const float* __restrict__ b4,
    const float* __restrict__ W5, const float* __restrict__ b5,
    const float* __restrict__ W6, const float* __restrict__ b6,
    float* __restrict__ out)          // [8,16384,2]
{
    extern __shared__ float smem[];
    float* xin  = smem + XIN_OFF;     // [37][64]
    float* bufA = smem + BUFA_OFF;    // [516][64]
    float* bufB = smem + BUFB_OFF;    // [256][64]

    const int tid = threadIdx.x;
    const int blk = blockIdx.x;
    const int b   = blk >> 8;              // 256 blocks per batch (16384/64)
    const int n0  = (blk & 255) * TM;

    // ---------------- Phase A: bilinear sampling -> x_in[37][64] ----------------
    // Reference samples swapaxes(img, 2, 3): value = img[b][c][x_idx][y_idx],
    // x_idx from coord.x, y_idx from coord.y, zero padding outside.
    {
        const int m = tid & 63;         // point within tile
        const int g = tid >> 6;         // channel group 0..7
        const int p = n0 + m;
        const float cx = coord[((size_t)b * Nn + p) * 2 + 0];
        const float cy = coord[((size_t)b * Nn + p) * 2 + 1];
        const float gx = (cx + 1.0f) * 32.0f - 0.5f;
        const float gy = (cy + 1.0f) * 32.0f - 0.5f;
        const float fx0 = floorf(gx), fy0 = floorf(gy);
        const float wx = gx - fx0, wy = gy - fy0;
        const int ix0 = (int)fx0, iy0 = (int)fy0;
        const int ix1 = ix0 + 1,  iy1 = iy0 + 1;
        const bool vx0 = ((unsigned)ix0 < 64u), vx1 = ((unsigned)ix1 < 64u);
        const bool vy0 = ((unsigned)iy0 < 64u), vy1 = ((unsigned)iy1 < 64u);
        const float w00 = (vx0 && vy0) ? (1.f - wx) * (1.f - wy) : 0.f;
        const float w10 = (vx1 && vy0) ? wx * (1.f - wy) : 0.f;
        const float w01 = (vx0 && vy1) ? (1.f - wx) * wy : 0.f;
        const float w11 = (vx1 && vy1) ? wx * wy : 0.f;
        const int cx0 = min(max(ix0, 0), 63), cx1 = min(max(ix1, 0), 63);
        const int cy0 = min(max(iy0, 0), 63), cy1 = min(max(iy1, 0), 63);
        const int o00 = cx0 * 64 + cy0, o10 = cx1 * 64 + cy0;
        const int o01 = cx0 * 64 + cy1, o11 = cx1 * 64 + cy1;

        if (g == 0) {
            xin[32 * 64 + m] = cx;
            xin[33 * 64 + m] = cy;
        }
        for (int ci = g; ci < 35; ci += 8) {
            const float* src;
            int k;
            if (ci < 32)      { src = ctx + (size_t)(b * CTXC + ci) * 4096;        k = ci; }
            else if (ci < 34) { src = lr  + (size_t)(b * OUTC + (ci - 32)) * 4096; k = 34 + (ci - 32); }
            else              { src = eps + (size_t)b * 4096;                      k = 36; }
            float v = w00 * __ldg(src + o00) + w10 * __ldg(src + o10)
                    + w01 * __ldg(src + o01) + w11 * __ldg(src + o11);
            xin[k * 64 + m] = v;
        }
    }
    __syncthreads();

    // ---------------- Phase B: MLP ----------------
    const int tx = tid & 15;   // 4 points each  -> 64 points
    const int ty = tid >> 4;   // 0..31, CPT cols each

    // L0: 37 -> 516  (passes: 256 + 256 + tail 4 cols)
    layer_pass<37, 516, 8, false>(W0, b0, xin, nullptr, bufA, tx, ty, 0);
    layer_pass<37, 516, 8, false>(W0, b0, xin, nullptr, bufA, tx, ty, 256);
    layer_pass<37, 516, 2, false>(W0, b0, xin, nullptr, bufA, tx, ty, 512);
    __syncthreads();
    // L1: 516+37 -> 256
    layer_pass<516, 256, 8, true>(W1, b1, bufA, xin, bufB, tx, ty, 0);
    __syncthreads();
    // L2: 256+37 -> 128
    layer_pass<256, 128, 4, true>(W2, b2, bufB, xin, bufA, tx, ty, 0);
    __syncthreads();
    // L3: 128+37 -> 64
    layer_pass<128, 64, 2, true>(W3, b3, bufA, xin, bufB, tx, ty, 0);
    __syncthreads();
    // L4: 64+37 -> 32   (ty < 16 active)
    layer_pass<64, 32, 2, true>(W4, b4, bufB, xin, bufA, tx, ty, 0);
    __syncthreads();
    // L5: 32+37 -> 16   (ty < 8 active)
    layer_pass<32, 16, 2, true>(W5, b5, bufA, xin, bufB, tx, ty, 0);
    __syncthreads();

    // ---------------- Final layer: [16] -> [2], no relu ----------------
    if (tid < 64) {
        const int m = tid;
        float s0 = __ldg(b6 + 0), s1 = __ldg(b6 + 1);
#pragma unroll
        for (int k = 0; k < 16; ++k) {
            const float a = bufB[k * 64 + m];
            s0 += a * __ldg(W6 + k * 2 + 0);
            s1 += a * __ldg(W6 + k * 2 + 1);
        }
        float2 o; o.x = s0; o.y = s1;
        *reinterpret_cast<float2*>(out + ((size_t)b * Nn + n0 + m) * 2) = o;
    }
}

extern "C" void kernel_launch(void* const* d_in, const int* in_sizes, int n_in,
                              void* d_out, int out_size) {
    (void)in_sizes; (void)n_in; (void)out_size;
    const float* lr    = (const float*)d_in[0];
    const float* ctx   = (const float*)d_in[1];
    const float* eps   = (const float*)d_in[2];
    const float* coord = (const float*)d_in[3];
    const float* W0 = (const float*)d_in[4];  const float* b0 = (const float*)d_in[5];
    const float* W1 = (const float*)d_in[6];  const float* b1 = (const float*)d_in[7];
    const float* W2 = (const float*)d_in[8];  const float* b2 = (const float*)d_in[9];
    const float* W3 = (const float*)d_in[10]; const float* b3 = (const float*)d_in[11];
    const float* W4 = (const float*)d_in[12]; const float* b4 = (const float*)d_in[13];
    const float* W5 = (const float*)d_in[14]; const float* b5 = (const float*)d_in[15];
    const float* W6 = (const float*)d_in[16]; const float* b6 = (const float*)d_in[17];
    float* out = (float*)d_out;

    cudaFuncSetAttribute(ContDecoder_15788299780267_kernel,
                         cudaFuncAttributeMaxDynamicSharedMemorySize, SMEM_BYTES);

    const int grid = (Bb * Nn) / TM;   // 2048 CTAs
    ContDecoder_15788299780267_kernel<<<grid, THREADS, SMEM_BYTES>>>(
        lr, ctx, eps, coord,
        W0, b0, W1, b1, W2, b2, W3, b3, W4, b4, W5, b5, W6, b6,
        out);
}